// round 13
// baseline (speedup 1.0000x reference)
#include <cuda_runtime.h>
#include <cuda_bf16.h>
#include <cstdint>

// RBF_Conv2d: x (16,1,256,256) f32, w (64,1,5,5) f32 -> out (16,64,252,252) f32
// out[b,o,h,w] = exp(-0.5 * d^2 / var_hw),  d = sqrt(max(||patch-w||^2,1e-12))
// var_hw = sample var (ddof=1) of d over the (B*O)=1024 matrix at pixel (h,w)
// Persistent h-strip blocks; redux.u32 warp reductions; Chan variance merge.
// sqrt and exp2 computed on FMA/ALU pipes (no MUFU) via Newton + poly.

#define B_  16
#define O_  64
#define HO  252
#define WO  252
#define WT  12      // w-pixels per block (252 = 21*12)
#define WIN 16      // window cols staged
#define NQ  6       // WT/2 packed pairs
#define STRIP 18    // h-rows per block (252 = 14*18)

#define SCALE2  1.099511627776e12f     // 2^40  (applied to d^2)
#define INV_S2  9.094947017729282e-13f // 2^-40
#define S2_RES  5.9604644775390625e-8f // 2^-24 (pass-2 rescale -> 2^16 fixed point)
#define S2_BACK 1.52587890625e-5f      // 2^-16

typedef unsigned long long u64;

__device__ __forceinline__ u64 fma2(u64 a, u64 b, u64 c) {
    u64 d; asm("fma.rn.f32x2 %0, %1, %2, %3;" : "=l"(d) : "l"(a), "l"(b), "l"(c)); return d;
}
__device__ __forceinline__ u64 add2(u64 a, u64 b) {
    u64 d; asm("add.rn.f32x2 %0, %1, %2;" : "=l"(d) : "l"(a), "l"(b)); return d;
}
__device__ __forceinline__ u64 pack2(float lo, float hi) {
    u64 d; asm("mov.b64 %0, {%1, %2};" : "=l"(d) : "f"(lo), "f"(hi)); return d;
}
__device__ __forceinline__ void unpack2(u64 v, float& lo, float& hi) {
    asm("mov.b64 {%0, %1}, %2;" : "=f"(lo), "=f"(hi) : "l"(v));
}
// odd-aligned pair {hi(a), lo(b)} built in registers (ALU pipe, no LDS)
__device__ __forceinline__ u64 mkodd(u64 a, u64 b) {
    u64 r;
    asm("{\n\t"
        ".reg .b32 alo, ahi, blo, bhi;\n\t"
        "mov.b64 {alo, ahi}, %1;\n\t"
        "mov.b64 {blo, bhi}, %2;\n\t"
        "mov.b64 %0, {ahi, blo};\n\t"
        "}" : "=l"(r) : "l"(a), "l"(b));
    return r;
}
__device__ __forceinline__ unsigned redux_u32(unsigned v) {
    unsigned r; asm("redux.sync.add.u32 %0, %1, 0xffffffff;" : "=r"(r) : "r"(v)); return r;
}

// sqrt without MUFU: rsqrt bit-seed + 3 Newton iterations (FMA/ALU pipes).
// a must be > 0 (we clamp to >= 1.0995 before calling). rel err ~1e-7.
__device__ __forceinline__ float fast_sqrt(float a) {
    float y = __int_as_float(0x5f3759df - (__float_as_int(a) >> 1));
    float nh = -0.5f * a;
    y = y * fmaf(nh, y * y, 1.5f);
    y = y * fmaf(nh, y * y, 1.5f);
    y = y * fmaf(nh, y * y, 1.5f);
    return a * y;
}

// exp2 without MUFU: magic-add range reduction + degree-6 poly on [-0.5,0.5]
// + integer exponent reconstruction. Input y <= 0; clamped to >= -100.
__device__ __forceinline__ float fast_exp2(float y) {
    y = fmaxf(y, -100.f);
    float t  = y + 12582912.f;           // 1.5*2^23: round-to-nearest
    float nf = t - 12582912.f;
    float f  = y - nf;                   // f in [-0.5, 0.5]
    float p  = 1.5403530e-4f;
    p = fmaf(p, f, 1.3333558e-3f);
    p = fmaf(p, f, 9.6181291e-3f);
    p = fmaf(p, f, 5.5504109e-2f);
    p = fmaf(p, f, 2.4022651e-1f);
    p = fmaf(p, f, 6.9314718e-1f);
    p = fmaf(p, f, 1.0f);
    int sc = __float_as_int(t) << 23;    // == n << 23 (low 9 bits of magic are 0)
    return __int_as_float(__float_as_int(p) + sc);
}

__global__ __launch_bounds__(512, 2)
void rbf_conv2d_kernel(const float* __restrict__ x,
                       const float* __restrict__ w,
                       float* __restrict__ out)
{
    __shared__ __align__(16) float xs [B_][6][WIN];  // rolling row buffer (6 slots)
    __shared__ __align__(16) float ws [25][O_];      // weights transposed [k][o]
    __shared__ __align__(16) float wns[O_];          // wn[o]*2^40
    __shared__ __align__(16) float pns[B_][WT];      // patch norms *2^40
    __shared__ __align__(16) float redC[WT][16];     // [w][warp] warp sums of d (2^20)
    __shared__ __align__(16) float redS[WT][16];     // [w][warp] warp S2 (2^16)
    __shared__ __align__(16) float cinv_s[WT];

    const int tid  = threadIdx.x;
    const int h0   = blockIdx.y * STRIP;
    const int w0   = blockIdx.x * WT;
    const int lane = tid & 31;
    const int warp = tid >> 5;           // == batch index b (warp-uniform)
    const int b    = warp;
    const int o0   = lane * 2;

    // ---- one-time staging: weights transposed + first 4 window rows ----
    for (int i = tid; i < 25 * O_; i += 512) {
        int k = i >> 6, o = i & 63;
        ws[k][o] = w[o * 25 + k];
    }
    for (int i = tid; i < B_ * 4 * WIN; i += 512) {
        int bb = i >> 6;
        int r  = (i >> 4) & 3;
        int c  = i & 15;
        xs[bb][r][c] = x[bb * 65536 + (h0 + r) * 256 + (w0 + c)];
    }
    // prefetch row h0+4 into registers
    float v = 0.f;
    const int pb = tid >> 4, pc = tid & 15;   // prefetch coords (tid<256)
    if (tid < 256)
        v = x[pb * 65536 + (h0 + 4) * 256 + (w0 + pc)];
    __syncthreads();

    // ---- weight norms (scaled 2^40), once ----
    if (tid < O_) {
        float s = 0.f;
        #pragma unroll
        for (int k = 0; k < 25; k++) {
            float t = ws[k][tid];
            s = fmaf(t, t, s);
        }
        wns[tid] = s * SCALE2;
    }

    const u64 m2 = pack2(-2.f * SCALE2, -2.f * SCALE2);

    for (int it = 0; it < STRIP; it++) {
        const int h = h0 + it;
        // slot indices for window rows h..h+4
        int sr[5];
        sr[0] = it % 6;
        #pragma unroll
        for (int r = 1; r < 5; r++) { sr[r] = sr[r - 1] + 1; if (sr[r] == 6) sr[r] = 0; }

        // ---- store prefetched row (h+4) into its slot ----
        if (tid < 256) xs[pb][sr[4]][pc] = v;
        __syncthreads();

        // ---- patch norms (192 threads), scaled 2^40 ----
        if (tid < B_ * WT) {
            int bb = tid / WT, wi = tid % WT;
            float s = 0.f;
            #pragma unroll
            for (int kh = 0; kh < 5; kh++) {
                const float* row = &xs[bb][sr[kh]][0];
                #pragma unroll
                for (int kw = 0; kw < 5; kw++) {
                    float t = row[wi + kw];
                    s = fmaf(t, t, s);
                }
            }
            pns[bb][wi] = s * SCALE2;
        }
        // ---- prefetch next row (h+5) — latency hidden behind mainloop ----
        if (tid < 256) {
            int row = h + 5; if (row > 255) row = 255;   // clamp; last value unused
            v = x[pb * 65536 + row * 256 + (w0 + pc)];
        }
        __syncthreads();

        // ---- mainloop: tile 1b x 2o x 12w (6 packed pairs) ----
        u64 acc0[NQ], acc1[NQ];
        #pragma unroll
        for (int q = 0; q < NQ; q++) { acc0[q] = 0ull; acc1[q] = 0ull; }

        #pragma unroll
        for (int kh = 0; kh < 5; kh++) {
            u64 ev[8];
            {
                const uint4* p = (const uint4*)&xs[b][sr[kh]][0];
                #pragma unroll
                for (int t = 0; t < 4; t++) {
                    uint4 q4 = p[t];
                    ev[2 * t]     = (u64)q4.x | ((u64)q4.y << 32);
                    ev[2 * t + 1] = (u64)q4.z | ((u64)q4.w << 32);
                }
            }
            u64 od[7];
            #pragma unroll
            for (int i = 0; i < 7; i++) od[i] = mkodd(ev[i], ev[i + 1]);

            #pragma unroll
            for (int kw = 0; kw < 5; kw++) {
                float2 wv = *(const float2*)&ws[kh * 5 + kw][o0];
                u64 wp0 = pack2(wv.x, wv.x);
                u64 wp1 = pack2(wv.y, wv.y);
                #pragma unroll
                for (int q = 0; q < NQ; q++) {
                    u64 m = ((kw & 1) == 0) ? ev[q + (kw >> 1)] : od[q + ((kw - 1) >> 1)];
                    acc0[q] = fma2(m, wp0, acc0[q]);
                    acc1[q] = fma2(m, wp1, acc1[q]);
                }
            }
        }

        // ---- d_s = sqrt(max(d2*2^40, 1.1)) = d*2^20; local per-w sums ----
        float2 wnv = *(const float2*)&wns[o0];
        float dist[2][WT];
        float sums[WT];
        #pragma unroll
        for (int wi = 0; wi < WT; wi++) sums[wi] = 0.f;

        const u64* pnp = (const u64*)&pns[b][0];
        #pragma unroll
        for (int j = 0; j < 2; j++) {
            const float wn = j ? wnv.y : wnv.x;
            const u64 wnp = pack2(wn, wn);
            #pragma unroll
            for (int q = 0; q < NQ; q++) {
                u64 d2p = fma2(j ? acc1[q] : acc0[q], m2, add2(pnp[q], wnp));
                float a, bb;
                unpack2(d2p, a, bb);
                a  = fmaxf(a,  1.0995f);     // 1e-12 * 2^40
                bb = fmaxf(bb, 1.0995f);
                float da = fast_sqrt(a);
                float db = fast_sqrt(bb);
                dist[j][2 * q]     = da;
                dist[j][2 * q + 1] = db;
                sums[2 * q]     += da;
                sums[2 * q + 1] += db;
            }
        }

        // ---- warp sum of d over 64 o's via u32 redux ----
        float csumf[WT];
        #pragma unroll
        for (int wi = 0; wi < WT; wi++) {
            unsigned su = __float2uint_rn(sums[wi]);
            csumf[wi] = __uint2float_rn(redux_u32(su));
        }
        if (lane == 0) {
            #pragma unroll
            for (int wi = 0; wi < WT; wi++) redC[wi][warp] = csumf[wi];
        }

        // ---- warp-local S2 = Σ(d - c_w)^2 (2^40 -> 2^16 fixed point) ----
        #pragma unroll
        for (int wi = 0; wi < WT; wi++) {
            float dd0 = fmaf(csumf[wi], -1.0f / 64.0f, dist[0][wi]);
            float dd1 = fmaf(csumf[wi], -1.0f / 64.0f, dist[1][wi]);
            float s2 = fmaf(dd1, dd1, dd0 * dd0);
            unsigned su = __float2uint_rn(s2 * S2_RES);
            unsigned r = redux_u32(su);
            if (lane == 0) redS[wi][warp] = __uint2float_rn(r);
        }
        __syncthreads();

        // ---- finalize (12 threads): Chan merge of 16 warp stats ----
        if (tid < WT) {
            const float4* cp = (const float4*)&redC[tid][0];
            float4 c0 = cp[0], c1 = cp[1], c2 = cp[2], c3 = cp[3];
            const float4* sp = (const float4*)&redS[tid][0];
            float4 s0 = sp[0], s1 = sp[1], s2v = sp[2], s3 = sp[3];
            float csum = ((c0.x + c0.y) + (c0.z + c0.w)) + ((c1.x + c1.y) + (c1.z + c1.w))
                       + ((c2.x + c2.y) + (c2.z + c2.w)) + ((c3.x + c3.y) + (c3.z + c3.w));
            float S2w  = ((s0.x + s0.y) + (s0.z + s0.w)) + ((s1.x + s1.y) + (s1.z + s1.w))
                       + ((s2v.x + s2v.y) + (s2v.z + s2v.w)) + ((s3.x + s3.y) + (s3.z + s3.w));
            float mean = csum * (1.0f / 1024.0f);
            float bsum = 0.f;
            float cw[16] = {c0.x, c0.y, c0.z, c0.w, c1.x, c1.y, c1.z, c1.w,
                            c2.x, c2.y, c2.z, c2.w, c3.x, c3.y, c3.z, c3.w};
            #pragma unroll
            for (int r = 0; r < 16; r++) {
                float dd = fmaf(cw[r], 1.0f / 64.0f, -mean);
                bsum = fmaf(dd, dd, bsum);
            }
            float S2tot = fmaf(S2w, S2_BACK, 64.0f * bsum * INV_S2);
            float var = S2tot * (1.0f / 1023.0f);
            // out = exp2( d^2 * (-0.5*log2(e)/var) ); d_s^2 = d^2 * 2^40
            cinv_s[tid] = (-0.72134752044448170368f * INV_S2) / var;
        }
        __syncthreads();

        float cl[WT];
        #pragma unroll
        for (int wi = 0; wi < WT; wi++) cl[wi] = cinv_s[wi];

        // ---- write out: per (b,o) 12 contiguous floats (float4 x3) ----
        #pragma unroll
        for (int j = 0; j < 2; j++) {
            size_t base = ((size_t)(b * O_ + (o0 + j)) * HO + h) * WO + w0;
            #pragma unroll
            for (int g = 0; g < WT; g += 4) {
                float d0 = dist[j][g + 0];
                float d1 = dist[j][g + 1];
                float d2v = dist[j][g + 2];
                float d3 = dist[j][g + 3];
                float4 vv;
                vv.x = fast_exp2(cl[g + 0] * d0 * d0);
                vv.y = fast_exp2(cl[g + 1] * d1 * d1);
                vv.z = fast_exp2(cl[g + 2] * d2v * d2v);
                vv.w = fast_exp2(cl[g + 3] * d3 * d3);
                *(float4*)&out[base + g] = vv;
            }
        }
    }
}

extern "C" void kernel_launch(void* const* d_in, const int* in_sizes, int n_in,
                              void* d_out, int out_size)
{
    const float* x = (const float*)d_in[0];      // (16,1,256,256)
    const float* w = (const float*)d_in[1];      // (64,1,5,5)
    float* out = (float*)d_out;                  // (16,64,252,252)

    dim3 grid(WO / WT, HO / STRIP);              // (21, 14) = 294 blocks, one wave
    rbf_conv2d_kernel<<<grid, 512>>>(x, w, out);
}

// round 14
// speedup vs baseline: 1.0428x; 1.0428x over previous
#include <cuda_runtime.h>
#include <cuda_bf16.h>
#include <cstdint>

// RBF_Conv2d: x (16,1,256,256) f32, w (64,1,5,5) f32 -> out (16,64,252,252) f32
// out[b,o,h,w] = exp(-0.5 * d^2 / var_hw),  d = sqrt(max(||patch-w||^2,1e-12))
// var_hw = sample var (ddof=1) of d over the (B*O)=1024 matrix at pixel (h,w)
// Persistent h-strip blocks; warp-local patch norms (3 barriers/iter);
// redux.u32 warp reductions; Chan variance merge; MUFU sqrt/ex2.

#define B_  16
#define O_  64
#define HO  252
#define WO  252
#define WT  12      // w-pixels per block (252 = 21*12)
#define WIN 16      // window cols staged
#define NQ  6       // WT/2 packed pairs
#define STRIP 18    // h-rows per block (252 = 14*18)

#define SCALE2  1.099511627776e12f     // 2^40  (applied to d^2)
#define INV_S2  9.094947017729282e-13f // 2^-40
#define S2_RES  5.9604644775390625e-8f // 2^-24 (pass-2 rescale -> 2^16 fixed point)
#define S2_BACK 1.52587890625e-5f      // 2^-16

typedef unsigned long long u64;

__device__ __forceinline__ u64 fma2(u64 a, u64 b, u64 c) {
    u64 d; asm("fma.rn.f32x2 %0, %1, %2, %3;" : "=l"(d) : "l"(a), "l"(b), "l"(c)); return d;
}
__device__ __forceinline__ u64 add2(u64 a, u64 b) {
    u64 d; asm("add.rn.f32x2 %0, %1, %2;" : "=l"(d) : "l"(a), "l"(b)); return d;
}
__device__ __forceinline__ u64 pack2(float lo, float hi) {
    u64 d; asm("mov.b64 %0, {%1, %2};" : "=l"(d) : "f"(lo), "f"(hi)); return d;
}
__device__ __forceinline__ void unpack2(u64 v, float& lo, float& hi) {
    asm("mov.b64 {%0, %1}, %2;" : "=f"(lo), "=f"(hi) : "l"(v));
}
// odd-aligned pair {hi(a), lo(b)} built in registers (ALU pipe, no LDS)
__device__ __forceinline__ u64 mkodd(u64 a, u64 b) {
    u64 r;
    asm("{\n\t"
        ".reg .b32 alo, ahi, blo, bhi;\n\t"
        "mov.b64 {alo, ahi}, %1;\n\t"
        "mov.b64 {blo, bhi}, %2;\n\t"
        "mov.b64 %0, {ahi, blo};\n\t"
        "}" : "=l"(r) : "l"(a), "l"(b));
    return r;
}
__device__ __forceinline__ unsigned redux_u32(unsigned v) {
    unsigned r; asm("redux.sync.add.u32 %0, %1, 0xffffffff;" : "=r"(r) : "r"(v)); return r;
}
__device__ __forceinline__ float ex2_approx(float a) {
    float r; asm("ex2.approx.ftz.f32 %0, %1;" : "=f"(r) : "f"(a)); return r;
}
__device__ __forceinline__ float sqrt_approx(float a) {
    float r; asm("sqrt.approx.ftz.f32 %0, %1;" : "=f"(r) : "f"(a)); return r;
}
__device__ __forceinline__ float rcp_approx(float a) {
    float r; asm("rcp.approx.ftz.f32 %0, %1;" : "=f"(r) : "f"(a)); return r;
}

__global__ __launch_bounds__(512, 2)
void rbf_conv2d_kernel(const float* __restrict__ x,
                       const float* __restrict__ w,
                       float* __restrict__ out)
{
    __shared__ __align__(16) float xs [B_][6][WIN];  // rolling row buffer (6 slots)
    __shared__ __align__(16) float ws [25][O_];      // weights transposed [k][o]
    __shared__ __align__(16) float wns[O_];          // wn[o]*2^40
    __shared__ __align__(16) float redC[WT][16];     // [w][warp] warp sums of d (2^20)
    __shared__ __align__(16) float redS[WT][16];     // [w][warp] warp S2 (2^16)
    __shared__ __align__(16) float cinv_s[WT];

    const int tid  = threadIdx.x;
    const int h0   = blockIdx.y * STRIP;
    const int w0   = blockIdx.x * WT;
    const int lane = tid & 31;
    const int warp = tid >> 5;           // == batch index b (warp-uniform)
    const int b    = warp;
    const int o0   = lane * 2;

    // ---- one-time staging: weights transposed + first 4 window rows ----
    for (int i = tid; i < 25 * O_; i += 512) {
        int k = i >> 6, o = i & 63;
        ws[k][o] = w[o * 25 + k];
    }
    for (int i = tid; i < B_ * 4 * WIN; i += 512) {
        int bb = i >> 6;
        int r  = (i >> 4) & 3;
        int c  = i & 15;
        xs[bb][r][c] = x[bb * 65536 + (h0 + r) * 256 + (w0 + c)];
    }
    // prefetch row h0+4 into registers
    float v = 0.f;
    const int pb = tid >> 4, pc = tid & 15;   // prefetch coords (tid<256)
    if (tid < 256)
        v = x[pb * 65536 + (h0 + 4) * 256 + (w0 + pc)];
    __syncthreads();

    // ---- weight norms (scaled 2^40), once ----
    if (tid < O_) {
        float s = 0.f;
        #pragma unroll
        for (int k = 0; k < 25; k++) {
            float t = ws[k][tid];
            s = fmaf(t, t, s);
        }
        wns[tid] = s * SCALE2;
    }

    const u64 m2 = pack2(-2.f * SCALE2, -2.f * SCALE2);

    for (int it = 0; it < STRIP; it++) {
        const int h = h0 + it;
        // slot indices for window rows h..h+4
        int sr[5];
        sr[0] = it % 6;
        #pragma unroll
        for (int r = 1; r < 5; r++) { sr[r] = sr[r - 1] + 1; if (sr[r] == 6) sr[r] = 0; }

        // ---- store prefetched row (h+4) into its slot ----
        if (tid < 256) xs[pb][sr[4]][pc] = v;
        __syncthreads();                           // B1: window ready

        // ---- issue next-row prefetch early (hides behind mainloop) ----
        if (tid < 256) {
            int row = h + 5; if (row > 255) row = 255;   // clamp; last value unused
            v = x[pb * 65536 + row * 256 + (w0 + pc)];
        }

        // ---- warp-local patch norms: lanes 0..11 compute pn for (b, lane) ----
        float pn_l = 0.f;
        {
            const int wi = lane < WT ? lane : 0;
            #pragma unroll
            for (int kh = 0; kh < 5; kh++) {
                const float* row = &xs[b][sr[kh]][wi];
                #pragma unroll
                for (int kw = 0; kw < 5; kw++) {
                    float t = row[kw];
                    pn_l = fmaf(t, t, pn_l);
                }
            }
            pn_l *= SCALE2;
        }
        u64 pnq[NQ];
        #pragma unroll
        for (int q = 0; q < NQ; q++) {
            float lo = __shfl_sync(0xffffffffu, pn_l, 2 * q);
            float hi = __shfl_sync(0xffffffffu, pn_l, 2 * q + 1);
            pnq[q] = pack2(lo, hi);
        }

        // ---- mainloop: tile 1b x 2o x 12w (6 packed pairs) ----
        u64 acc0[NQ], acc1[NQ];
        #pragma unroll
        for (int q = 0; q < NQ; q++) { acc0[q] = 0ull; acc1[q] = 0ull; }

        #pragma unroll
        for (int kh = 0; kh < 5; kh++) {
            u64 ev[8];
            {
                const uint4* p = (const uint4*)&xs[b][sr[kh]][0];
                #pragma unroll
                for (int t = 0; t < 4; t++) {
                    uint4 q4 = p[t];
                    ev[2 * t]     = (u64)q4.x | ((u64)q4.y << 32);
                    ev[2 * t + 1] = (u64)q4.z | ((u64)q4.w << 32);
                }
            }
            u64 od[7];
            #pragma unroll
            for (int i = 0; i < 7; i++) od[i] = mkodd(ev[i], ev[i + 1]);

            #pragma unroll
            for (int kw = 0; kw < 5; kw++) {
                float2 wv = *(const float2*)&ws[kh * 5 + kw][o0];
                u64 wp0 = pack2(wv.x, wv.x);
                u64 wp1 = pack2(wv.y, wv.y);
                #pragma unroll
                for (int q = 0; q < NQ; q++) {
                    u64 m = ((kw & 1) == 0) ? ev[q + (kw >> 1)] : od[q + ((kw - 1) >> 1)];
                    acc0[q] = fma2(m, wp0, acc0[q]);
                    acc1[q] = fma2(m, wp1, acc1[q]);
                }
            }
        }

        // ---- d_s = sqrt(max(d2*2^40, 1.1)) = d*2^20; local per-w sums ----
        float2 wnv = *(const float2*)&wns[o0];
        float dist[2][WT];
        float sums[WT];
        #pragma unroll
        for (int wi = 0; wi < WT; wi++) sums[wi] = 0.f;

        #pragma unroll
        for (int j = 0; j < 2; j++) {
            const float wn = j ? wnv.y : wnv.x;
            const u64 wnp = pack2(wn, wn);
            #pragma unroll
            for (int q = 0; q < NQ; q++) {
                u64 d2p = fma2(j ? acc1[q] : acc0[q], m2, add2(pnq[q], wnp));
                float a, bb;
                unpack2(d2p, a, bb);
                a  = fmaxf(a,  1.0995f);     // 1e-12 * 2^40
                bb = fmaxf(bb, 1.0995f);
                float da = sqrt_approx(a);
                float db = sqrt_approx(bb);
                dist[j][2 * q]     = da;
                dist[j][2 * q + 1] = db;
                sums[2 * q]     += da;
                sums[2 * q + 1] += db;
            }
        }

        // ---- warp sum of d over 64 o's via u32 redux ----
        float csumf[WT];
        #pragma unroll
        for (int wi = 0; wi < WT; wi++) {
            unsigned su = __float2uint_rn(sums[wi]);
            csumf[wi] = __uint2float_rn(redux_u32(su));
        }
        if (lane == 0) {
            #pragma unroll
            for (int wi = 0; wi < WT; wi++) redC[wi][warp] = csumf[wi];
        }

        // ---- warp-local S2 = Σ(d - c_w)^2 (2^40 -> 2^16 fixed point) ----
        #pragma unroll
        for (int wi = 0; wi < WT; wi++) {
            float dd0 = fmaf(csumf[wi], -1.0f / 64.0f, dist[0][wi]);
            float dd1 = fmaf(csumf[wi], -1.0f / 64.0f, dist[1][wi]);
            float s2 = fmaf(dd1, dd1, dd0 * dd0);
            unsigned su = __float2uint_rn(s2 * S2_RES);
            unsigned r = redux_u32(su);
            if (lane == 0) redS[wi][warp] = __uint2float_rn(r);
        }
        __syncthreads();                           // B2: warp stats ready

        // ---- finalize (12 threads): Chan merge of 16 warp stats ----
        if (tid < WT) {
            const float4* cp = (const float4*)&redC[tid][0];
            float4 c0 = cp[0], c1 = cp[1], c2 = cp[2], c3 = cp[3];
            const float4* sp = (const float4*)&redS[tid][0];
            float4 s0 = sp[0], s1 = sp[1], s2v = sp[2], s3 = sp[3];
            float csum = ((c0.x + c0.y) + (c0.z + c0.w)) + ((c1.x + c1.y) + (c1.z + c1.w))
                       + ((c2.x + c2.y) + (c2.z + c2.w)) + ((c3.x + c3.y) + (c3.z + c3.w));
            float S2w  = ((s0.x + s0.y) + (s0.z + s0.w)) + ((s1.x + s1.y) + (s1.z + s1.w))
                       + ((s2v.x + s2v.y) + (s2v.z + s2v.w)) + ((s3.x + s3.y) + (s3.z + s3.w));
            float mean = csum * (1.0f / 1024.0f);
            float bsum = 0.f;
            float cw[16] = {c0.x, c0.y, c0.z, c0.w, c1.x, c1.y, c1.z, c1.w,
                            c2.x, c2.y, c2.z, c2.w, c3.x, c3.y, c3.z, c3.w};
            #pragma unroll
            for (int r = 0; r < 16; r++) {
                float dd = fmaf(cw[r], 1.0f / 64.0f, -mean);
                bsum = fmaf(dd, dd, bsum);
            }
            float S2tot = fmaf(S2w, S2_BACK, 64.0f * bsum * INV_S2);
            float var = S2tot * (1.0f / 1023.0f);
            // out = exp2( d^2 * (-0.5*log2(e)/var) ); d_s^2 = d^2 * 2^40
            cinv_s[tid] = (-0.72134752044448170368f * INV_S2) * rcp_approx(var);
        }
        __syncthreads();                           // B3: cinv ready

        float cl[WT];
        #pragma unroll
        for (int wi = 0; wi < WT; wi++) cl[wi] = cinv_s[wi];

        // ---- write out: per (b,o) 12 contiguous floats (float4 x3) ----
        #pragma unroll
        for (int j = 0; j < 2; j++) {
            size_t base = ((size_t)(b * O_ + (o0 + j)) * HO + h) * WO + w0;
            #pragma unroll
            for (int g = 0; g < WT; g += 4) {
                float d0 = dist[j][g + 0];
                float d1 = dist[j][g + 1];
                float d2v = dist[j][g + 2];
                float d3 = dist[j][g + 3];
                float4 vv;
                vv.x = ex2_approx(cl[g + 0] * d0 * d0);
                vv.y = ex2_approx(cl[g + 1] * d1 * d1);
                vv.z = ex2_approx(cl[g + 2] * d2v * d2v);
                vv.w = ex2_approx(cl[g + 3] * d3 * d3);
                *(float4*)&out[base + g] = vv;
            }
        }
    }
}

extern "C" void kernel_launch(void* const* d_in, const int* in_sizes, int n_in,
                              void* d_out, int out_size)
{
    const float* x = (const float*)d_in[0];      // (16,1,256,256)
    const float* w = (const float*)d_in[1];      // (64,1,5,5)
    float* out = (float*)d_out;                  // (16,64,252,252)

    dim3 grid(WO / WT, HO / STRIP);              // (21, 14) = 294 blocks, one wave
    rbf_conv2d_kernel<<<grid, 512>>>(x, w, out);
}

// round 16
// speedup vs baseline: 1.0520x; 1.0087x over previous
#include <cuda_runtime.h>
#include <cuda_bf16.h>
#include <cstdint>

// RBF_Conv2d: x (16,1,256,256) f32, w (64,1,5,5) f32 -> out (16,64,252,252) f32
// out[b,o,h,w] = exp(-0.5 * d^2 / var_hw),  d = sqrt(max(||patch-w||^2,1e-12))
// var_hw = sample var (ddof=1) of d over the (B*O)=1024 matrix at pixel (h,w)
// Persistent h-strip blocks, 2 barriers/iter: finalize overlapped with row staging.
// redux.u32 warp reductions; Chan variance merge; MUFU sqrt/ex2/rcp.

#define B_  16
#define O_  64
#define HO  252
#define WO  252
#define WT  12      // w-pixels per block (252 = 21*12)
#define WIN 16      // window cols staged
#define NQ  6       // WT/2 packed pairs
#define STRIP 18    // h-rows per block (252 = 14*18)

#define SCALE2  1.099511627776e12f     // 2^40  (applied to d^2)
#define INV_S2  9.094947017729282e-13f // 2^-40
#define S2_RES  5.9604644775390625e-8f // 2^-24 (pass-2 rescale -> 2^16 fixed point)
#define S2_BACK 1.52587890625e-5f      // 2^-16

typedef unsigned long long u64;

__device__ __forceinline__ u64 fma2(u64 a, u64 b, u64 c) {
    u64 d; asm("fma.rn.f32x2 %0, %1, %2, %3;" : "=l"(d) : "l"(a), "l"(b), "l"(c)); return d;
}
__device__ __forceinline__ u64 add2(u64 a, u64 b) {
    u64 d; asm("add.rn.f32x2 %0, %1, %2;" : "=l"(d) : "l"(a), "l"(b)); return d;
}
__device__ __forceinline__ u64 pack2(float lo, float hi) {
    u64 d; asm("mov.b64 %0, {%1, %2};" : "=l"(d) : "f"(lo), "f"(hi)); return d;
}
__device__ __forceinline__ void unpack2(u64 v, float& lo, float& hi) {
    asm("mov.b64 {%0, %1}, %2;" : "=f"(lo), "=f"(hi) : "l"(v));
}
// odd-aligned pair {hi(a), lo(b)} built in registers (ALU pipe, no LDS)
__device__ __forceinline__ u64 mkodd(u64 a, u64 b) {
    u64 r;
    asm("{\n\t"
        ".reg .b32 alo, ahi, blo, bhi;\n\t"
        "mov.b64 {alo, ahi}, %1;\n\t"
        "mov.b64 {blo, bhi}, %2;\n\t"
        "mov.b64 %0, {ahi, blo};\n\t"
        "}" : "=l"(r) : "l"(a), "l"(b));
    return r;
}
__device__ __forceinline__ unsigned redux_u32(unsigned v) {
    unsigned r; asm("redux.sync.add.u32 %0, %1, 0xffffffff;" : "=r"(r) : "r"(v)); return r;
}
__device__ __forceinline__ float ex2_approx(float a) {
    float r; asm("ex2.approx.ftz.f32 %0, %1;" : "=f"(r) : "f"(a)); return r;
}
__device__ __forceinline__ float sqrt_approx(float a) {
    float r; asm("sqrt.approx.ftz.f32 %0, %1;" : "=f"(r) : "f"(a)); return r;
}
__device__ __forceinline__ float rcp_approx(float a) {
    float r; asm("rcp.approx.ftz.f32 %0, %1;" : "=f"(r) : "f"(a)); return r;
}

__global__ __launch_bounds__(512, 2)
void rbf_conv2d_kernel(const float* __restrict__ x,
                       const float* __restrict__ w,
                       float* __restrict__ out)
{
    __shared__ __align__(16) float xs [B_][6][WIN];  // rolling row buffer (6 slots)
    __shared__ __align__(16) float ws [25][O_];      // weights transposed [k][o]
    __shared__ __align__(16) float wns[O_];          // wn[o]*2^40
    __shared__ __align__(16) float pns[B_][WT];      // patch norms *2^40 (per-warp)
    __shared__ __align__(16) float redC[WT][16];     // [w][warp] warp sums of d (2^20)
    __shared__ __align__(16) float redS[WT][16];     // [w][warp] warp S2 (2^16)
    __shared__ __align__(16) float cinv_s[WT];

    const int tid  = threadIdx.x;
    const int h0   = blockIdx.y * STRIP;
    const int w0   = blockIdx.x * WT;
    const int lane = tid & 31;
    const int warp = tid >> 5;           // == batch index b (warp-uniform)
    const int b    = warp;
    const int o0   = lane * 2;

    // ---- prologue: stage weights + first 5 window rows, prefetch row 5 ----
    for (int i = tid; i < 25 * O_; i += 512) {
        int k = i >> 6, o = i & 63;
        ws[k][o] = w[o * 25 + k];
    }
    for (int i = tid; i < B_ * 5 * WIN; i += 512) {
        int bb = i / (5 * WIN);
        int r  = (i / WIN) % 5;
        int c  = i & 15;
        xs[bb][r][c] = x[bb * 65536 + (h0 + r) * 256 + (w0 + c)];
    }
    float v = 0.f;
    const int pb = tid >> 4, pc = tid & 15;   // prefetch coords (tid<256)
    if (tid < 256) {
        int row = h0 + 5; if (row > 255) row = 255;
        v = x[pb * 65536 + row * 256 + (w0 + pc)];
    }
    __syncthreads();

    if (tid < O_) {
        float s = 0.f;
        #pragma unroll
        for (int k = 0; k < 25; k++) {
            float t = ws[k][tid];
            s = fmaf(t, t, s);
        }
        wns[tid] = s * SCALE2;
    }
    __syncthreads();

    const u64 m2 = pack2(-2.f * SCALE2, -2.f * SCALE2);

    for (int it = 0; it < STRIP; it++) {
        const int h = h0 + it;
        int sr[5];
        sr[0] = it % 6;
        #pragma unroll
        for (int r = 1; r < 5; r++) { sr[r] = sr[r - 1] + 1; if (sr[r] == 6) sr[r] = 0; }

        // ================= compute phase =================
        // ---- per-warp patch norms: lanes 0..11, STS + syncwarp (no block barrier) ----
        if (lane < WT) {
            float s = 0.f;
            #pragma unroll
            for (int kh = 0; kh < 5; kh++) {
                const float* row = &xs[b][sr[kh]][lane];
                #pragma unroll
                for (int kw = 0; kw < 5; kw++) {
                    float t = row[kw];
                    s = fmaf(t, t, s);
                }
            }
            pns[b][lane] = s * SCALE2;
        }
        __syncwarp();

        // ---- mainloop: tile 1b x 2o x 12w (6 packed pairs) ----
        u64 acc0[NQ], acc1[NQ];
        #pragma unroll
        for (int q = 0; q < NQ; q++) { acc0[q] = 0ull; acc1[q] = 0ull; }

        #pragma unroll
        for (int kh = 0; kh < 5; kh++) {
            u64 ev[8];
            {
                const uint4* p = (const uint4*)&xs[b][sr[kh]][0];
                #pragma unroll
                for (int t = 0; t < 4; t++) {
                    uint4 q4 = p[t];
                    ev[2 * t]     = (u64)q4.x | ((u64)q4.y << 32);
                    ev[2 * t + 1] = (u64)q4.z | ((u64)q4.w << 32);
                }
            }
            u64 od[7];
            #pragma unroll
            for (int i = 0; i < 7; i++) od[i] = mkodd(ev[i], ev[i + 1]);

            #pragma unroll
            for (int kw = 0; kw < 5; kw++) {
                float2 wv = *(const float2*)&ws[kh * 5 + kw][o0];
                u64 wp0 = pack2(wv.x, wv.x);
                u64 wp1 = pack2(wv.y, wv.y);
                #pragma unroll
                for (int q = 0; q < NQ; q++) {
                    u64 m = ((kw & 1) == 0) ? ev[q + (kw >> 1)] : od[q + ((kw - 1) >> 1)];
                    acc0[q] = fma2(m, wp0, acc0[q]);
                    acc1[q] = fma2(m, wp1, acc1[q]);
                }
            }
        }

        // ---- d_s = sqrt(max(d2*2^40, 1.1)) = d*2^20; local per-w sums ----
        float2 wnv = *(const float2*)&wns[o0];
        float dist[2][WT];
        float sums[WT];
        #pragma unroll
        for (int wi = 0; wi < WT; wi++) sums[wi] = 0.f;

        const u64* pnp = (const u64*)&pns[b][0];
        #pragma unroll
        for (int j = 0; j < 2; j++) {
            const float wn = j ? wnv.y : wnv.x;
            const u64 wnp = pack2(wn, wn);
            #pragma unroll
            for (int q = 0; q < NQ; q++) {
                u64 d2p = fma2(j ? acc1[q] : acc0[q], m2, add2(pnp[q], wnp));
                float a, bb;
                unpack2(d2p, a, bb);
                a  = fmaxf(a,  1.0995f);     // 1e-12 * 2^40
                bb = fmaxf(bb, 1.0995f);
                float da = sqrt_approx(a);
                float db = sqrt_approx(bb);
                dist[j][2 * q]     = da;
                dist[j][2 * q + 1] = db;
                sums[2 * q]     += da;
                sums[2 * q + 1] += db;
            }
        }

        // ---- warp sum of d over 64 o's via u32 redux ----
        float csumf[WT];
        #pragma unroll
        for (int wi = 0; wi < WT; wi++) {
            unsigned su = __float2uint_rn(sums[wi]);
            csumf[wi] = __uint2float_rn(redux_u32(su));
        }
        if (lane == 0) {
            #pragma unroll
            for (int wi = 0; wi < WT; wi++) redC[wi][warp] = csumf[wi];
        }

        // ---- warp-local S2 = Σ(d - c_w)^2 (2^40 -> 2^16 fixed point) ----
        #pragma unroll
        for (int wi = 0; wi < WT; wi++) {
            float dd0 = fmaf(csumf[wi], -1.0f / 64.0f, dist[0][wi]);
            float dd1 = fmaf(csumf[wi], -1.0f / 64.0f, dist[1][wi]);
            float s2 = fmaf(dd1, dd1, dd0 * dd0);
            unsigned su = __float2uint_rn(s2 * S2_RES);
            unsigned r = redux_u32(su);
            if (lane == 0) redS[wi][warp] = __uint2float_rn(r);
        }
        __syncthreads();                 // B1: stats visible; old row slot free

        // ================= par phase (overlapped) =================
        if (tid < WT) {
            // finalize: Chan merge of 16 warp stats
            const float4* cp = (const float4*)&redC[tid][0];
            float4 c0 = cp[0], c1 = cp[1], c2 = cp[2], c3 = cp[3];
            const float4* sp = (const float4*)&redS[tid][0];
            float4 s0 = sp[0], s1 = sp[1], s2v = sp[2], s3 = sp[3];
            float csum = ((c0.x + c0.y) + (c0.z + c0.w)) + ((c1.x + c1.y) + (c1.z + c1.w))
                       + ((c2.x + c2.y) + (c2.z + c2.w)) + ((c3.x + c3.y) + (c3.z + c3.w));
            float S2w  = ((s0.x + s0.y) + (s0.z + s0.w)) + ((s1.x + s1.y) + (s1.z + s1.w))
                       + ((s2v.x + s2v.y) + (s2v.z + s2v.w)) + ((s3.x + s3.y) + (s3.z + s3.w));
            float mean = csum * (1.0f / 1024.0f);
            float bsum = 0.f;
            float cw[16] = {c0.x, c0.y, c0.z, c0.w, c1.x, c1.y, c1.z, c1.w,
                            c2.x, c2.y, c2.z, c2.w, c3.x, c3.y, c3.z, c3.w};
            #pragma unroll
            for (int r = 0; r < 16; r++) {
                float dd = fmaf(cw[r], 1.0f / 64.0f, -mean);
                bsum = fmaf(dd, dd, bsum);
            }
            float S2tot = fmaf(S2w, S2_BACK, 64.0f * bsum * INV_S2);
            float var = S2tot * (1.0f / 1023.0f);
            cinv_s[tid] = (-0.72134752044448170368f * INV_S2) * rcp_approx(var);
        } else if (tid >= 256 && tid < 268) {
            // nothing: keep warp 8 lanes free for row store below (tid<256 path)
        }
        if (tid < 256) {
            // store prefetched row (h+5) into slot (it+5)%6; issue next prefetch
            int s5 = sr[4] + 1; if (s5 == 6) s5 = 0;
            xs[pb][s5][pc] = v;
            int row = h + 6; if (row > 255) row = 255;   // clamp; tail never read
            v = x[pb * 65536 + row * 256 + (w0 + pc)];
        }
        __syncthreads();                 // B2: cinv + new row ready

        // ================= output phase =================
        float cl[WT];
        #pragma unroll
        for (int wi = 0; wi < WT; wi++) cl[wi] = cinv_s[wi];

        #pragma unroll
        for (int j = 0; j < 2; j++) {
            size_t base = ((size_t)(b * O_ + (o0 + j)) * HO + h) * WO + w0;
            #pragma unroll
            for (int g = 0; g < WT; g += 4) {
                float d0 = dist[j][g + 0];
                float d1 = dist[j][g + 1];
                float d2v = dist[j][g + 2];
                float d3 = dist[j][g + 3];
                float4 vv;
                vv.x = ex2_approx(cl[g + 0] * d0 * d0);
                vv.y = ex2_approx(cl[g + 1] * d1 * d1);
                vv.z = ex2_approx(cl[g + 2] * d2v * d2v);
                vv.w = ex2_approx(cl[g + 3] * d3 * d3);
                *(float4*)&out[base + g] = vv;
            }
        }
    }
}

extern "C" void kernel_launch(void* const* d_in, const int* in_sizes, int n_in,
                              void* d_out, int out_size)
{
    const float* x = (const float*)d_in[0];      // (16,1,256,256)
    const float* w = (const float*)d_in[1];      // (64,1,5,5)
    float* out = (float*)d_out;                  // (16,64,252,252)

    dim3 grid(WO / WT, HO / STRIP);              // (21, 14) = 294 blocks, one wave
    rbf_conv2d_kernel<<<grid, 512>>>(x, w, out);
}